// round 9
// baseline (speedup 1.0000x reference)
#include <cuda_runtime.h>
#include <math.h>

#define BATCH 256
#define SEQT  512
#define NIN   256
#define HID   256
#define G3    768
#define NLAYER 2
#define MTOT  (BATCH * SEQT)
#define NBLK_RECUR 256u

typedef unsigned long long ull;

// ---------------- scratch (device globals; no allocation) ----------------
__device__ float g_weff[NLAYER][NIN * G3];        // [l][k][n]
__device__ float g_ueffT[NLAYER][G3 * HID];       // [l][n][k]
__device__ float g_wx[SEQT * BATCH * G3];         // [t][b][768]
__device__ float g_x1[HID * MTOT];                // layer-0 output, [j][m] (m = b*T+t)
__device__ float g_hst[2][BATCH * HID];           // [p][b][k]
__device__ unsigned int g_bar_count = 0;
__device__ unsigned int g_done_count = 0;

// ---------------- helpers ----------------
__device__ __forceinline__ void cp16(void* smem_dst, const void* gmem_src) {
    unsigned s = (unsigned)__cvta_generic_to_shared(smem_dst);
    asm volatile("cp.async.ca.shared.global [%0], [%1], 16;" :: "r"(s), "l"(gmem_src));
}
__device__ __forceinline__ void cp_commit() { asm volatile("cp.async.commit_group;"); }
template<int N> __device__ __forceinline__ void cp_wait() {
    asm volatile("cp.async.wait_group %0;" :: "n"(N));
}
__device__ __forceinline__ void bar_red() {
    asm volatile("red.release.gpu.add.u32 [%0], 1;" :: "l"(&g_bar_count) : "memory");
}
__device__ __forceinline__ unsigned bar_ld() {
    unsigned v;
    asm volatile("ld.acquire.gpu.u32 %0, [%1];" : "=r"(v) : "l"(&g_bar_count) : "memory");
    return v;
}
__device__ __forceinline__ float sigmoid_f(float x) {
    return __fdividef(1.f, 1.f + __expf(-x));
}
__device__ __forceinline__ float tanh_f(float x) {
    return __fdividef(2.f, 1.f + __expf(-2.f * x)) - 1.f;
}
// packed fp32x2 fma: d.lo += a.lo*b.lo ; d.hi += a.hi*b.hi
__device__ __forceinline__ void fma2(ull& d, ull a, ull b) {
    asm("fma.rn.f32x2 %0, %1, %2, %0;" : "+l"(d) : "l"(a), "l"(b));
}
__device__ __forceinline__ float pairsum(ull v) {
    float2 f = *(float2*)&v;
    return f.x + f.y;
}

// ---------------- effective weight precompute ----------------
__global__ void eff_weights_kernel(const float* __restrict__ Wd, const float* __restrict__ Wdg,
                                   const float* __restrict__ Wo, const float* __restrict__ Wog,
                                   const float* __restrict__ Ud, const float* __restrict__ Udg,
                                   const float* __restrict__ Uo, const float* __restrict__ Uog)
{
    int idx = blockIdx.x * blockDim.x + threadIdx.x;
    int n = idx % G3;
    int k = (idx / G3) % NIN;
    int l = idx / (G3 * NIN);
    {
        float s = 0.f;
        const float* wd  = Wd  + (l * NIN + k) * 64;
        const float* wdg = Wdg + l * 64 * G3 + n;
        #pragma unroll 8
        for (int r = 0; r < 64; r++) s = fmaf(wd[r], wdg[r * G3], s);
        const float* wo  = Wo  + (l * NIN + k) * 32;
        const float* wog = Wog + l * 32 * G3 + n;
        #pragma unroll 8
        for (int r = 0; r < 32; r++) s = fmaf(wo[r], wog[r * G3], s);
        g_weff[l][k * G3 + n] = s;
    }
    {
        float s = 0.f;
        const float* ud  = Ud  + (l * HID + k) * 64;
        const float* udg = Udg + l * 64 * G3 + n;
        #pragma unroll 8
        for (int r = 0; r < 64; r++) s = fmaf(ud[r], udg[r * G3], s);
        const float* uo  = Uo  + (l * HID + k) * 32;
        const float* uog = Uog + l * 32 * G3 + n;
        #pragma unroll 8
        for (int r = 0; r < 32; r++) s = fmaf(uo[r], uog[r * G3], s);
        g_ueffT[l][n * HID + k] = s;
    }
}

// ---------------- wx GEMM (k-pair packed f32x2) ----------------
#define BM 128
#define BN 128
#define BK 16
__global__ void __launch_bounds__(256) wx_gemm_kernel(const float* __restrict__ X0,
                                                      const float* __restrict__ bias,
                                                      int layer)
{
    __shared__ __align__(16) float2 As2[8][BM];   // [k-pair][m] : (A[2p][m], A[2p+1][m])
    __shared__ __align__(16) float2 Bs2[8][BN];   // [k-pair][n]

    const float* __restrict__ W = g_weff[layer];

    const int tid = threadIdx.x;
    const int tx = tid & 15;
    const int ty = tid >> 4;
    const int n0 = blockIdx.x * BN;
    const int m0 = blockIdx.y * BM;

    ull acc2[8][8];
    #pragma unroll
    for (int i = 0; i < 8; i++)
        #pragma unroll
        for (int j = 0; j < 8; j++) acc2[i][j] = 0ull;

    for (int kc = 0; kc < NIN; kc += BK) {
        // ---- A tile ----
        if (layer == 0) {
            #pragma unroll
            for (int i = 0; i < 2; i++) {
                int t = tid + i * 256;             // 0..511
                int m = t >> 2;                    // 0..127
                int k4 = (t & 3) << 2;             // 0,4,8,12
                float4 v = *(const float4*)(X0 + (size_t)(m0 + m) * NIN + kc + k4);
                As2[(k4 >> 1) + 0][m] = make_float2(v.x, v.y);
                As2[(k4 >> 1) + 1][m] = make_float2(v.z, v.w);
            }
        } else {
            // g_x1 is [k][m]: interleave two consecutive k rows
            int kk2 = tid >> 5;                    // 0..7
            int m4 = (tid & 31) << 2;              // 0..124
            float4 e = *(const float4*)(g_x1 + (size_t)(kc + 2 * kk2)     * MTOT + m0 + m4);
            float4 o = *(const float4*)(g_x1 + (size_t)(kc + 2 * kk2 + 1) * MTOT + m0 + m4);
            As2[kk2][m4 + 0] = make_float2(e.x, o.x);
            As2[kk2][m4 + 1] = make_float2(e.y, o.y);
            As2[kk2][m4 + 2] = make_float2(e.z, o.z);
            As2[kk2][m4 + 3] = make_float2(e.w, o.w);
        }
        // ---- B tile ----
        {
            int kk2 = tid >> 5;
            int n4 = (tid & 31) << 2;
            float4 e = *(const float4*)(W + (size_t)(kc + 2 * kk2)     * G3 + n0 + n4);
            float4 o = *(const float4*)(W + (size_t)(kc + 2 * kk2 + 1) * G3 + n0 + n4);
            Bs2[kk2][n4 + 0] = make_float2(e.x, o.x);
            Bs2[kk2][n4 + 1] = make_float2(e.y, o.y);
            Bs2[kk2][n4 + 2] = make_float2(e.z, o.z);
            Bs2[kk2][n4 + 3] = make_float2(e.w, o.w);
        }
        __syncthreads();
        #pragma unroll
        for (int kk2 = 0; kk2 < 8; kk2++) {
            ull a2[8], b2[8];
            *(ulonglong2*)&a2[0] = *(const ulonglong2*)&As2[kk2][ty * 4];
            *(ulonglong2*)&a2[2] = *(const ulonglong2*)&As2[kk2][ty * 4 + 2];
            *(ulonglong2*)&a2[4] = *(const ulonglong2*)&As2[kk2][64 + ty * 4];
            *(ulonglong2*)&a2[6] = *(const ulonglong2*)&As2[kk2][64 + ty * 4 + 2];
            *(ulonglong2*)&b2[0] = *(const ulonglong2*)&Bs2[kk2][tx * 4];
            *(ulonglong2*)&b2[2] = *(const ulonglong2*)&Bs2[kk2][tx * 4 + 2];
            *(ulonglong2*)&b2[4] = *(const ulonglong2*)&Bs2[kk2][64 + tx * 4];
            *(ulonglong2*)&b2[6] = *(const ulonglong2*)&Bs2[kk2][64 + tx * 4 + 2];
            #pragma unroll
            for (int i = 0; i < 8; i++)
                #pragma unroll
                for (int j = 0; j < 8; j++) fma2(acc2[i][j], a2[i], b2[j]);
        }
        __syncthreads();
    }

    float bv[8];
    #pragma unroll
    for (int j = 0; j < 8; j++) {
        int n = n0 + ((j < 4) ? tx * 4 + j : 64 + tx * 4 + (j - 4));
        bv[j] = bias[n];
    }
    #pragma unroll
    for (int i = 0; i < 8; i++) {
        int m = m0 + ((i < 4) ? ty * 4 + i : 64 + ty * 4 + (i - 4));
        int bidx = m >> 9;
        int tt   = m & 511;
        float* orow = g_wx + ((size_t)tt * BATCH + bidx) * G3 + n0;
        float4 v0 = make_float4(pairsum(acc2[i][0]) + bv[0], pairsum(acc2[i][1]) + bv[1],
                                pairsum(acc2[i][2]) + bv[2], pairsum(acc2[i][3]) + bv[3]);
        float4 v1 = make_float4(pairsum(acc2[i][4]) + bv[4], pairsum(acc2[i][5]) + bv[5],
                                pairsum(acc2[i][6]) + bv[6], pairsum(acc2[i][7]) + bv[7]);
        *(float4*)(orow + tx * 4) = v0;
        *(float4*)(orow + 64 + tx * 4) = v1;
    }
}

// ---------------- persistent recurrence kernel (f32x2 + swizzled h) ----------------
// grid (8, 32): blockIdx.x -> 32 batch rows, blockIdx.y -> 8 hidden cols.
// warp w handles j0 = j_base + 2w, j0+1 for all 32 b (lane = b).
__global__ void __launch_bounds__(128, 2) recur_kernel(float* __restrict__ out, int layer)
{
    __shared__ __align__(16) float su[24][260];       // U tile (broadcast reads)
    __shared__ __align__(16) float sh[2][32][64];     // h chunks, XOR-swizzled rows

    const int tid = threadIdx.x;
    const int lane = tid & 31;
    const int w = tid >> 5;
    const int b_base = blockIdx.x << 5;
    const int j_base = blockIdx.y << 3;
    const int b = b_base + lane;
    const int j0 = j_base + (w << 1);
    const int hswz = (lane & 7) << 2;                 // read-side swizzle for own row

    const float* __restrict__ uT = g_ueffT[layer];
    float* __restrict__ hout = out + (size_t)MTOT * HID;

    // load U tile once: 24 rows (3 gates x 8 j) x 256 k
    for (int q = tid; q < 24 * 64; q += 128) {
        int row = q >> 6;
        int c4 = (q & 63) << 2;
        int g = row >> 3, jl = row & 7;
        *(float4*)&su[row][c4] = *(const float4*)(uT + ((size_t)((g << 8) + j_base + jl)) * HID + c4);
    }

    // zero-init g_hst[0] patch owned by this block
    #pragma unroll
    for (int i = 0; i < 2; i++) {
        int idx = tid + (i << 7);
        int bb = idx >> 3, jj = idx & 7;
        g_hst[0][(b_base + bb) * HID + j_base + jj] = 0.f;
    }

    unsigned barIdx = 0;
    __threadfence();
    __syncthreads();
    if (tid == 0) {
        bar_red();
        unsigned tgt = (++barIdx) * NBLK_RECUR;
        while (bar_ld() < tgt) {}
    } else barIdx++;
    __syncthreads();

    float hp0 = 0.f, hp1 = 0.f;
    float xb0[8], xb1[8];
    int p = 0;

    for (int t = 0; t < SEQT; t++) {
        const float* __restrict__ hg = g_hst[p];
        float* __restrict__ hw = g_hst[p ^ 1];

        // wx prefetch (independent of h)
        const float* wrow = g_wx + ((size_t)t * BATCH + b) * G3;
        float2 wz = *(const float2*)&wrow[j0];
        float2 wr = *(const float2*)&wrow[HID + j0];
        float2 wc = *(const float2*)&wrow[2 * HID + j0];

        // issue h chunks 0 and 1 via cp.async (swizzled destinations)
        #pragma unroll
        for (int i = 0; i < 4; i++) {
            int e = tid + (i << 7);
            int row = e >> 4, c4 = (e & 15) << 2;
            int c4s = c4 ^ ((row & 7) << 2);
            cp16(&sh[0][row][c4s], hg + (b_base + row) * HID + c4);
        }
        cp_commit();
        #pragma unroll
        for (int i = 0; i < 4; i++) {
            int e = tid + (i << 7);
            int row = e >> 4, c4 = (e & 15) << 2;
            int c4s = c4 ^ ((row & 7) << 2);
            cp16(&sh[1][row][c4s], hg + (b_base + row) * HID + 64 + c4);
        }
        cp_commit();

        ull az0 = 0ull, ar0 = 0ull, ac0 = 0ull, az1 = 0ull, ar1 = 0ull, ac1 = 0ull;

        #pragma unroll
        for (int kc = 0; kc < 4; kc++) {
            if (kc < 3) cp_wait<1>(); else cp_wait<0>();
            __syncthreads();

            const int cur = kc & 1;
            const int kb = kc << 6;
            const float* uzp0 = &su[(w << 1)][kb];
            const float* uzp1 = &su[(w << 1) + 1][kb];
            const float* urp0 = &su[8 + (w << 1)][kb];
            const float* urp1 = &su[8 + (w << 1) + 1][kb];
            const float* ucp0 = &su[16 + (w << 1)][kb];
            const float* ucp1 = &su[16 + (w << 1) + 1][kb];
            const float* hr = &sh[cur][lane][0];
            #pragma unroll
            for (int kk = 0; kk < 64; kk += 4) {
                ulonglong2 hv = *(const ulonglong2*)&hr[kk ^ hswz];
                ulonglong2 u0 = *(const ulonglong2*)&uzp0[kk];
                fma2(az0, hv.x, u0.x); fma2(az0, hv.y, u0.y);
                ulonglong2 u1 = *(const ulonglong2*)&urp0[kk];
                fma2(ar0, hv.x, u1.x); fma2(ar0, hv.y, u1.y);
                ulonglong2 u2 = *(const ulonglong2*)&ucp0[kk];
                fma2(ac0, hv.x, u2.x); fma2(ac0, hv.y, u2.y);
                ulonglong2 u3 = *(const ulonglong2*)&uzp1[kk];
                fma2(az1, hv.x, u3.x); fma2(az1, hv.y, u3.y);
                ulonglong2 u4 = *(const ulonglong2*)&urp1[kk];
                fma2(ar1, hv.x, u4.x); fma2(ar1, hv.y, u4.y);
                ulonglong2 u5 = *(const ulonglong2*)&ucp1[kk];
                fma2(ac1, hv.x, u5.x); fma2(ac1, hv.y, u5.y);
            }

            if (kc < 2) {
                __syncthreads();   // all done reading buf(cur) before refill
                #pragma unroll
                for (int i = 0; i < 4; i++) {
                    int e = tid + (i << 7);
                    int row = e >> 4, c4 = (e & 15) << 2;
                    int c4s = c4 ^ ((row & 7) << 2);
                    cp16(&sh[cur][row][c4s], hg + (b_base + row) * HID + ((kc + 2) << 6) + c4);
                }
                cp_commit();
            }
        }

        // gate math
        float z0 = sigmoid_f(wz.x + pairsum(az0));
        float r0 = sigmoid_f(wr.x + pairsum(ar0));
        float c0 = tanh_f(wc.x + r0 * pairsum(ac0));
        float hn0 = fmaf(z0, hp0 - c0, c0);

        float z1 = sigmoid_f(wz.y + pairsum(az1));
        float r1 = sigmoid_f(wr.y + pairsum(ar1));
        float c1 = tanh_f(wc.y + r1 * pairsum(ac1));
        float hn1 = fmaf(z1, hp1 - c1, c1);

        if (t < SEQT - 1) {
            *(float2*)&hw[b * HID + j0] = make_float2(hn0, hn1);
            __threadfence();
            __syncthreads();
            if (tid == 0) bar_red();
        }

        // sequence output (consumed only by later kernel launches)
        int ph = t & 7;
        if (layer == 0) {
            xb0[ph] = hn0; xb1[ph] = hn1;
            if (ph == 7) {
                size_t mb = (size_t)b * SEQT + (t - 7);
                float* r0p = g_x1 + (size_t)j0 * MTOT + mb;
                float* r1p = g_x1 + (size_t)(j0 + 1) * MTOT + mb;
                *(float4*)r0p       = make_float4(xb0[0], xb0[1], xb0[2], xb0[3]);
                *(float4*)(r0p + 4) = make_float4(xb0[4], xb0[5], xb0[6], xb0[7]);
                *(float4*)r1p       = make_float4(xb1[0], xb1[1], xb1[2], xb1[3]);
                *(float4*)(r1p + 4) = make_float4(xb1[4], xb1[5], xb1[6], xb1[7]);
            }
        } else {
            *(float2*)&out[((size_t)b * SEQT + t) * HID + j0] = make_float2(hn0, hn1);
        }
        if (t == SEQT - 1)
            *(float2*)&hout[b * (NLAYER * HID) + layer * HID + j0] = make_float2(hn0, hn1);

        if (t < SEQT - 1) {
            if (tid == 0) {
                unsigned tgt = (++barIdx) * NBLK_RECUR;
                while (bar_ld() < tgt) {}
            } else barIdx++;
            __syncthreads();
        }

        hp0 = hn0; hp1 = hn1;
        p ^= 1;
    }

    // ---- end-of-kernel reset protocol ----
    __syncthreads();
    if (tid == 0) {
        __threadfence();
        asm volatile("red.release.gpu.add.u32 [%0], 1;" :: "l"(&g_done_count) : "memory");
        if (blockIdx.x == 0 && blockIdx.y == 0) {
            unsigned v;
            do {
                asm volatile("ld.acquire.gpu.u32 %0, [%1];" : "=r"(v) : "l"(&g_done_count) : "memory");
            } while (v < NBLK_RECUR);
            g_bar_count = 0u;
            g_done_count = 0u;
            __threadfence();
        }
    }
}

// ---------------- launch ----------------
extern "C" void kernel_launch(void* const* d_in, const int* in_sizes, int n_in,
                              void* d_out, int out_size)
{
    const float* x   = (const float*)d_in[0];
    const float* Wd  = (const float*)d_in[1];
    const float* Wdg = (const float*)d_in[2];
    const float* Wo  = (const float*)d_in[3];
    const float* Wog = (const float*)d_in[4];
    const float* Ud  = (const float*)d_in[5];
    const float* Udg = (const float*)d_in[6];
    const float* Uo  = (const float*)d_in[7];
    const float* Uog = (const float*)d_in[8];
    const float* bb  = (const float*)d_in[9];
    float* out = (float*)d_out;

    eff_weights_kernel<<<(NLAYER * NIN * G3) / 256, 256>>>(Wd, Wdg, Wo, Wog, Ud, Udg, Uo, Uog);

    for (int l = 0; l < NLAYER; l++) {
        wx_gemm_kernel<<<dim3(G3 / BN, MTOT / BM), 256>>>(x, bb + l * G3, l);
        recur_kernel<<<dim3(8, 32), 128>>>(out, l);
    }
}